// round 8
// baseline (speedup 1.0000x reference)
#include <cuda_runtime.h>
#include <math_constants.h>

// Problem constants
#define BDIM 4
#define TDIM 512
#define VDIM 32000
#define NPAIR (BDIM * TDIM)        // 2048 (b,t) pairs
#define VC 8                       // v-chunks (grid.x)
#define TT 32                      // t-tile per block (one warp lane per t)
#define NWARP 8                    // warps per block
#define VPC (VDIM / VC)            // 4000 v per chunk
#define VPW (VPC / NWARP)          // 500 v per warp

#define LS 0.1f                    // label smoothing
#define MARGIN 0.6f
#define SSCALE 0.1f
#define KCONST 1000000.0f
#define WRAP_IGNORE (VDIM - 100)   // jnp .at[-100] wraps to 31900

#define OFF_TRUE  (NPAIR)          // d_out layout: loss | true_count | all_count
#define OFF_ALL   (NPAIR + VDIM)

// Scratch (static __device__ — no allocations allowed)
__device__ float g_sx[NPAIR * VC];
__device__ float g_se[NPAIR * VC];
__device__ float g_xt[NPAIR * VC];
__device__ float g_mx[NPAIR * VC];
__device__ int   g_am[NPAIR * VC];
__device__ float g_loss[NPAIR];
__device__ int   g_minocc[BDIM];
__device__ int   g_is64;           // 1 if index buffers are int64-layout

// Flag-selected index load: works for int32 buffers and for int64 buffers
// (little-endian low word; valid for values >= -2^31).
__device__ __forceinline__ int load_idx(const int* __restrict__ p, int i, int is64) {
    return is64 ? p[2 * i] : p[i];
}

// ---------------------------------------------------------------------------
// Kernel D: detect int32 vs int64 layout of target from its first 32 pairs.
// int64 layout: every odd 32-bit word is the high half of a small value
// (0 for >=0, -1 for negatives). int32 layout: odd words are random targets
// in [0,32000) -> essentially impossible that all 32 are 0/-1.
// ---------------------------------------------------------------------------
__global__ void k_detect(const int* __restrict__ tgt) {
    int all_hi = 1;
    #pragma unroll
    for (int i = 0; i < 32; ++i) {
        int w = tgt[2 * i + 1];               // within 2048*4 bytes either way
        if (w != 0 && w != -1) { all_hi = 0; break; }
    }
    g_is64 = all_hi;
}

// ---------------------------------------------------------------------------
// Kernel 0: zero the count region of d_out, init per-batch min-occur to +inf
// ---------------------------------------------------------------------------
__global__ void k_init(float* __restrict__ out, int out_size) {
    int i = blockIdx.x * blockDim.x + threadIdx.x;
    if (i < 2 * VDIM && (NPAIR + i) < out_size) out[NPAIR + i] = 0.0f;
    if (i < BDIM) g_minocc[i] = 0x7F800000;   // +inf bits
}

// ---------------------------------------------------------------------------
// Kernel 1: streaming partial reduction over v.
// grid = (VC, T/TT, B), block = 256 (8 warps). Lane -> t offset, warp -> v slice.
// Each thread accumulates over VPW=500 v-rows for its single t:
//   sum(x), sum(exp(x)), max/argmax, x[target] (if target in range).
// Loads: 32 lanes x consecutive t -> one 128B line per LDG, fully coalesced.
// ---------------------------------------------------------------------------
__global__ __launch_bounds__(256, 8)
void k_partial(const float* __restrict__ inp,
               const int* __restrict__ target) {
    const int chunk = blockIdx.x;
    const int tile  = blockIdx.y;
    const int b     = blockIdx.z;
    const int w     = threadIdx.x >> 5;
    const int lane  = threadIdx.x & 31;
    const int t     = tile * TT + lane;

    const int is64 = g_is64;
    const int tgt  = load_idx(target, b * TDIM + t, is64);
    const int v0   = chunk * VPC + w * VPW;

    const float* p = inp + ((size_t)b * VDIM + (size_t)v0) * TDIM + t;

    float sx = 0.0f, se = 0.0f, xt = 0.0f;
    float mx = -CUDART_INF_F;
    int   am = 0;

    #pragma unroll 4
    for (int i = 0; i < VPW; ++i) {
        float x = __ldg(p + (size_t)i * TDIM);
        int   v = v0 + i;
        sx += x;
        se += __expf(x);
        if (x > mx) { mx = x; am = v; }
        if (v == tgt) xt = x;
    }

    // combine the 8 warps' partials per lane (per t)
    __shared__ float s_sx[NWARP][TT + 1];
    __shared__ float s_se[NWARP][TT + 1];
    __shared__ float s_xt[NWARP][TT + 1];
    __shared__ float s_mx[NWARP][TT + 1];
    __shared__ int   s_am[NWARP][TT + 1];

    s_sx[w][lane] = sx;
    s_se[w][lane] = se;
    s_xt[w][lane] = xt;
    s_mx[w][lane] = mx;
    s_am[w][lane] = am;
    __syncthreads();

    if (w == 0) {
        float SX = 0.0f, SE = 0.0f, XT = 0.0f;
        float MX = -CUDART_INF_F;
        int   AM = 0;
        #pragma unroll
        for (int j = 0; j < NWARP; ++j) {   // ascending v -> first-index ties
            SX += s_sx[j][lane];
            SE += s_se[j][lane];
            XT += s_xt[j][lane];
            float m = s_mx[j][lane];
            if (m > MX) { MX = m; AM = s_am[j][lane]; }
        }
        int idx = (b * TDIM + t) * VC + chunk;
        g_sx[idx] = SX;
        g_se[idx] = SE;
        g_xt[idx] = XT;
        g_mx[idx] = MX;
        g_am[idx] = AM;
    }
}

// ---------------------------------------------------------------------------
// Kernel 2: per-(b,t) finalize: lse, occur, pre-sw loss, counts, min-occur.
// ---------------------------------------------------------------------------
__global__ void k_combine(const float* __restrict__ weight,
                          const int* __restrict__ target,
                          const int* __restrict__ seq_len,
                          float* __restrict__ out, int out_size) {
    int i = blockIdx.x * blockDim.x + threadIdx.x;
    if (i >= NPAIR) return;
    int b = i / TDIM;
    int t = i % TDIM;
    const int is64 = g_is64;

    float SX = 0.0f, SE = 0.0f, XT = 0.0f;
    float MX = -CUDART_INF_F;
    int   AM = 0;
    #pragma unroll
    for (int c = 0; c < VC; ++c) {          // ascending v chunks
        int idx = i * VC + c;
        SX += g_sx[idx];
        SE += g_se[idx];
        XT += g_xt[idx];
        float m = g_mx[idx];
        if (m > MX) { MX = m; AM = g_am[idx]; }
    }

    float lse    = logf(SE);                 // no shift: inputs N(0,1), safe
    float logp_t = XT - lse;
    float occur  = __expf(logp_t);
    float nll    = -logp_t;
    // -sum(logp) - nll = V*lse - SX + logp_t
    float false_mean = ((float)VDIM * lse - SX + logp_t) / (float)(VDIM - 1);

    int  tgi  = load_idx(target, i, is64);
    float mask = (tgi != -100) ? 1.0f : 0.0f;

    // weight index: jnp weight[-100] would wrap; clamp into range for safety
    int  wi = tgi;
    if (wi < 0) wi += VDIM;
    if (wi < 0 || wi >= VDIM) wi = 0;

    float loss = (nll * (1.0f - LS) + false_mean * LS) * mask;
    loss *= weight[wi];
    float om = 1.0f - occur;
    loss *= om * om;                         // GAMMA = 2
    g_loss[i] = loss;

    // histogram counts (fp adds of 1.0 are exact); wrap negative like jnp .at[]
    int ci = tgi;
    if (ci < 0) ci += VDIM;
    if (ci >= 0 && ci < VDIM) {
        if ((OFF_ALL + ci) < out_size) atomicAdd(&out[OFF_ALL + ci], 1.0f);
        if (AM == tgi && (OFF_TRUE + ci) < out_size)
            atomicAdd(&out[OFF_TRUE + ci], 1.0f);
    }

    // sentence weight: max_t sigmoid(K*(M-occur)) == sigmoid(K*(M - min occur))
    int sl = load_idx(seq_len, b, is64);
    if (t < sl) {
        atomicMin(&g_minocc[b], __float_as_int(occur));  // occur > 0: int order ok
    }
}

// ---------------------------------------------------------------------------
// Kernel 3: apply sentence scaling, write final loss, zero wrapped ignore idx.
// ---------------------------------------------------------------------------
__global__ void k_final(float* __restrict__ out, int out_size) {
    int i = blockIdx.x * blockDim.x + threadIdx.x;
    if (i >= NPAIR) return;
    int b = i / TDIM;
    float mo = __int_as_float(g_minocc[b]);
    float z  = KCONST * (MARGIN - mo);
    float sw = 1.0f / (1.0f + __expf(-z));   // saturates cleanly at 0 / 1
    sw = fminf(fmaxf(sw, SSCALE), 1.0f);
    if (i < out_size) out[i] = g_loss[i] * sw;

    if (i == 0) {                             // .at[-100] wraps to 31900
        if ((OFF_TRUE + WRAP_IGNORE) < out_size) out[OFF_TRUE + WRAP_IGNORE] = 0.0f;
        if ((OFF_ALL  + WRAP_IGNORE) < out_size) out[OFF_ALL  + WRAP_IGNORE] = 0.0f;
    }
}

// ---------------------------------------------------------------------------
extern "C" void kernel_launch(void* const* d_in, const int* in_sizes, int n_in,
                              void* d_out, int out_size) {
    // Identify inputs by element count (order-robust):
    //   input   : 4*32000*512 = 65,536,000
    //   weight  : 32,000
    //   target  : 2,048
    //   seq_len : 4
    const float* inp     = nullptr;
    const float* weight  = nullptr;
    const int*   target  = nullptr;
    const int*   seq_len = nullptr;
    for (int i = 0; i < n_in; ++i) {
        switch (in_sizes[i]) {
            case BDIM * VDIM * (long long)TDIM > 0x7FFFFFFF ? -1 : BDIM * VDIM * TDIM:
                inp = (const float*)d_in[i]; break;
            case VDIM:   weight  = (const float*)d_in[i]; break;
            case NPAIR:  target  = (const int*)d_in[i];   break;
            case BDIM:   seq_len = (const int*)d_in[i];   break;
            default: break;
        }
    }
    // Positional fallback (metadata order: input, weight, target, seq_len)
    if (!inp     && n_in > 0) inp     = (const float*)d_in[0];
    if (!weight  && n_in > 1) weight  = (const float*)d_in[1];
    if (!target  && n_in > 2) target  = (const int*)d_in[2];
    if (!seq_len && n_in > 3) seq_len = (const int*)d_in[3];

    float* out = (float*)d_out;

    k_detect<<<1, 1>>>(target);

    k_init<<<(2 * VDIM + 255) / 256, 256>>>(out, out_size);

    dim3 grid(VC, TDIM / TT, BDIM);
    k_partial<<<grid, 256>>>(inp, target);

    k_combine<<<(NPAIR + 255) / 256, 256>>>(weight, target, seq_len, out, out_size);

    k_final<<<(NPAIR + 255) / 256, 256>>>(out, out_size);
}

// round 9
// speedup vs baseline: 1.8526x; 1.8526x over previous
#include <cuda_runtime.h>
#include <math_constants.h>

// Problem constants
#define BDIM 4
#define TDIM 512
#define VDIM 32000
#define NPAIR (BDIM * TDIM)        // 2048 (b,t) pairs
#define VC 32                      // v-chunks (grid.x) == warp width for combine
#define NWARP 8                    // warps per block (split v)
#define TTB 128                    // t per block (32 lanes x float4)
#define VPC (VDIM / VC)            // 1000 v per chunk
#define VPW (VPC / NWARP)          // 125 v per warp

#define LS 0.1f
#define MARGIN 0.6f
#define SSCALE 0.1f
#define KCONST 1000000.0f
#define WRAP_IGNORE (VDIM - 100)   // jnp .at[-100] wraps to 31900

#define OFF_TRUE  (NPAIR)          // d_out layout: loss | true_count | all_count
#define OFF_ALL   (NPAIR + VDIM)

// Scratch (static __device__ — no allocations allowed)
__device__ float g_sx[NPAIR * VC];
__device__ float g_se[NPAIR * VC];
__device__ float g_xt[NPAIR * VC];
__device__ float g_mx[NPAIR * VC];
__device__ int   g_am[NPAIR * VC];
__device__ float g_loss[NPAIR];
__device__ int   g_minocc[BDIM];
__device__ int   g_is64;           // 1 if index buffers are int64-layout

// Flag-selected index load: works for int32 buffers and for int64 buffers
// (little-endian low word; valid for values >= -2^31).
__device__ __forceinline__ int load_idx(const int* __restrict__ p, int i, int is64) {
    return is64 ? p[2 * i] : p[i];
}

// ---------------------------------------------------------------------------
// Kernel D: detect int32 vs int64 layout of target from its first 32 pairs.
// ---------------------------------------------------------------------------
__global__ void k_detect(const int* __restrict__ tgt) {
    int all_hi = 1;
    #pragma unroll
    for (int i = 0; i < 32; ++i) {
        int w = tgt[2 * i + 1];               // within 2048*4 bytes either way
        if (w != 0 && w != -1) { all_hi = 0; break; }
    }
    g_is64 = all_hi;
}

// ---------------------------------------------------------------------------
// Kernel 0: zero the count region of d_out, init per-batch min-occur to +inf
// ---------------------------------------------------------------------------
__global__ void k_init(float* __restrict__ out, int out_size) {
    int i = blockIdx.x * blockDim.x + threadIdx.x;
    if (i < 2 * VDIM && (NPAIR + i) < out_size) out[NPAIR + i] = 0.0f;
    if (i < BDIM) g_minocc[i] = 0x7F800000;   // +inf bits
}

// ---------------------------------------------------------------------------
// Kernel 1: streaming partial reduction over v (the 262 MB pass).
// grid = (VC, T/TTB, B), block = 256 (8 warps).
// Lane owns 4 consecutive t via float4 (LDG.128, 512 B per warp-load),
// warps split v. 64 regs/thread (occ cap 4) so ptxas can front-batch loads.
// ---------------------------------------------------------------------------
__global__ __launch_bounds__(256, 4)
void k_partial(const float* __restrict__ inp,
               const int* __restrict__ target) {
    const int chunk = blockIdx.x;          // 0..VC-1
    const int tile  = blockIdx.y;          // 0..3
    const int b     = blockIdx.z;
    const int w     = threadIdx.x >> 5;
    const int lane  = threadIdx.x & 31;
    const int t0    = tile * TTB + lane * 4;

    const int is64 = g_is64;
    int tgt[4];
    #pragma unroll
    for (int j = 0; j < 4; ++j)
        tgt[j] = load_idx(target, b * TDIM + t0 + j, is64);

    const int v0 = chunk * VPC + w * VPW;
    const float4* p =
        (const float4*)(inp + ((size_t)b * VDIM + (size_t)v0) * TDIM + t0);

    float sx[4] = {0.f, 0.f, 0.f, 0.f};
    float se[4] = {0.f, 0.f, 0.f, 0.f};
    float xt[4] = {0.f, 0.f, 0.f, 0.f};
    float mx[4];
    int   am[4] = {0, 0, 0, 0};
    #pragma unroll
    for (int j = 0; j < 4; ++j) mx[j] = -CUDART_INF_F;

    #pragma unroll 5
    for (int i = 0; i < VPW; ++i) {
        float4 x = __ldg(p + (size_t)i * (TDIM / 4));
        const int v = v0 + i;
        float xs[4] = {x.x, x.y, x.z, x.w};
        #pragma unroll
        for (int j = 0; j < 4; ++j) {
            sx[j] += xs[j];
            se[j] += __expf(xs[j]);
            if (xs[j] > mx[j]) { mx[j] = xs[j]; am[j] = v; }
            if (v == tgt[j]) xt[j] = xs[j];
        }
    }

    // cross-warp combine per t (8 warps -> 1)
    __shared__ float s_sx[NWARP][TTB];
    __shared__ float s_se[NWARP][TTB];
    __shared__ float s_xt[NWARP][TTB];
    __shared__ float s_mx[NWARP][TTB];
    __shared__ int   s_am[NWARP][TTB];

    #pragma unroll
    for (int j = 0; j < 4; ++j) {
        int tt = lane * 4 + j;
        s_sx[w][tt] = sx[j];
        s_se[w][tt] = se[j];
        s_xt[w][tt] = xt[j];
        s_mx[w][tt] = mx[j];
        s_am[w][tt] = am[j];
    }
    __syncthreads();

    if (w == 0) {
        #pragma unroll
        for (int j = 0; j < 4; ++j) {
            int tt = lane * 4 + j;
            float SX = 0.f, SE = 0.f, XT = 0.f;
            float MX = -CUDART_INF_F;
            int   AM = 0;
            #pragma unroll
            for (int jw = 0; jw < NWARP; ++jw) {   // ascending v -> first-index ties
                SX += s_sx[jw][tt];
                SE += s_se[jw][tt];
                XT += s_xt[jw][tt];
                float m = s_mx[jw][tt];
                if (m > MX) { MX = m; AM = s_am[jw][tt]; }
            }
            int pair = b * TDIM + tile * TTB + tt;
            int idx  = pair * VC + chunk;
            g_sx[idx] = SX;
            g_se[idx] = SE;
            g_xt[idx] = XT;
            g_mx[idx] = MX;
            g_am[idx] = AM;
        }
    }
}

// ---------------------------------------------------------------------------
// Kernel 2: warp-per-(b,t): lane = chunk, coalesced loads, shuffle reduce,
// then per-pair finalize: lse, occur, pre-sw loss, counts, min-occur.
// ---------------------------------------------------------------------------
__global__ void k_combine(const float* __restrict__ weight,
                          const int* __restrict__ target,
                          const int* __restrict__ seq_len,
                          float* __restrict__ out, int out_size) {
    const int gid  = blockIdx.x * blockDim.x + threadIdx.x;
    const int pair = gid >> 5;                  // one warp per (b,t)
    const int lane = threadIdx.x & 31;          // lane = chunk (VC == 32)
    if (pair >= NPAIR) return;

    const int idx = pair * VC + lane;           // coalesced 128B per warp
    float SX = g_sx[idx];
    float SE = g_se[idx];
    float XT = g_xt[idx];
    float MX = g_mx[idx];
    int   AM = g_am[idx];

    #pragma unroll
    for (int off = 16; off > 0; off >>= 1) {
        SX += __shfl_down_sync(0xFFFFFFFFu, SX, off);
        SE += __shfl_down_sync(0xFFFFFFFFu, SE, off);
        XT += __shfl_down_sync(0xFFFFFFFFu, XT, off);
        float m = __shfl_down_sync(0xFFFFFFFFu, MX, off);
        int   a = __shfl_down_sync(0xFFFFFFFFu, AM, off);
        if (m > MX) { MX = m; AM = a; }          // strict > keeps lower chunk on tie
    }

    if (lane != 0) return;

    const int is64 = g_is64;
    const int b = pair / TDIM;
    const int t = pair % TDIM;

    float lse    = logf(SE);                 // no shift: inputs N(0,1), safe
    float logp_t = XT - lse;
    float occur  = __expf(logp_t);
    float nll    = -logp_t;
    // -sum(logp) - nll = V*lse - SX + logp_t
    float false_mean = ((float)VDIM * lse - SX + logp_t) / (float)(VDIM - 1);

    int   tgi  = load_idx(target, pair, is64);
    float mask = (tgi != -100) ? 1.0f : 0.0f;

    int wi = tgi;
    if (wi < 0) wi += VDIM;
    if (wi < 0 || wi >= VDIM) wi = 0;

    float loss = (nll * (1.0f - LS) + false_mean * LS) * mask;
    loss *= weight[wi];
    float om = 1.0f - occur;
    loss *= om * om;                         // GAMMA = 2
    g_loss[pair] = loss;

    // histogram counts (fp adds of 1.0 are exact); wrap negative like jnp .at[]
    int ci = tgi;
    if (ci < 0) ci += VDIM;
    if (ci >= 0 && ci < VDIM) {
        if ((OFF_ALL + ci) < out_size) atomicAdd(&out[OFF_ALL + ci], 1.0f);
        if (AM == tgi && (OFF_TRUE + ci) < out_size)
            atomicAdd(&out[OFF_TRUE + ci], 1.0f);
    }

    // sentence weight: max_t sigmoid(K*(M-occur)) == sigmoid(K*(M - min occur))
    int sl = load_idx(seq_len, b, is64);
    if (t < sl) {
        atomicMin(&g_minocc[b], __float_as_int(occur));  // occur > 0: int order ok
    }
}

// ---------------------------------------------------------------------------
// Kernel 3: apply sentence scaling, write final loss, zero wrapped ignore idx.
// ---------------------------------------------------------------------------
__global__ void k_final(float* __restrict__ out, int out_size) {
    int i = blockIdx.x * blockDim.x + threadIdx.x;
    if (i >= NPAIR) return;
    int b = i / TDIM;
    float mo = __int_as_float(g_minocc[b]);
    float z  = KCONST * (MARGIN - mo);
    float sw = 1.0f / (1.0f + __expf(-z));   // saturates cleanly at 0 / 1
    sw = fminf(fmaxf(sw, SSCALE), 1.0f);
    if (i < out_size) out[i] = g_loss[i] * sw;

    if (i == 0) {                             // .at[-100] wraps to 31900
        if ((OFF_TRUE + WRAP_IGNORE) < out_size) out[OFF_TRUE + WRAP_IGNORE] = 0.0f;
        if ((OFF_ALL  + WRAP_IGNORE) < out_size) out[OFF_ALL  + WRAP_IGNORE] = 0.0f;
    }
}

// ---------------------------------------------------------------------------
extern "C" void kernel_launch(void* const* d_in, const int* in_sizes, int n_in,
                              void* d_out, int out_size) {
    // Identify inputs by element count (order-robust):
    //   input 65,536,000 | weight 32,000 | target 2,048 | seq_len 4
    const float* inp     = nullptr;
    const float* weight  = nullptr;
    const int*   target  = nullptr;
    const int*   seq_len = nullptr;
    const int INP_N = BDIM * VDIM * TDIM;
    for (int i = 0; i < n_in; ++i) {
        int s = in_sizes[i];
        if      (s == INP_N) inp     = (const float*)d_in[i];
        else if (s == VDIM)  weight  = (const float*)d_in[i];
        else if (s == NPAIR) target  = (const int*)d_in[i];
        else if (s == BDIM)  seq_len = (const int*)d_in[i];
    }
    // Positional fallback (metadata order: input, weight, target, seq_len)
    if (!inp     && n_in > 0) inp     = (const float*)d_in[0];
    if (!weight  && n_in > 1) weight  = (const float*)d_in[1];
    if (!target  && n_in > 2) target  = (const int*)d_in[2];
    if (!seq_len && n_in > 3) seq_len = (const int*)d_in[3];

    float* out = (float*)d_out;

    k_detect<<<1, 1>>>(target);

    k_init<<<(2 * VDIM + 255) / 256, 256>>>(out, out_size);

    dim3 grid(VC, TDIM / TTB, BDIM);     // (32, 4, 4) = 512 blocks
    k_partial<<<grid, 256>>>(inp, target);

    k_combine<<<(NPAIR * 32 + 255) / 256, 256>>>(weight, target, seq_len, out, out_size);

    k_final<<<(NPAIR + 255) / 256, 256>>>(out, out_size);
}